// round 4
// baseline (speedup 1.0000x reference)
#include <cuda_runtime.h>

#define B_SZ   16384
#define T_SZ   79
#define H_SZ   256
#define CTA_ROWS 64
#define NTHREADS 256
#define NCTAS  (B_SZ / CTA_ROWS)   // 256

typedef unsigned long long ull;

// ---- packed f32x2 helpers (Blackwell FFMA2 path; ptxas only emits FFMA2 from PTX f32x2) ----
__device__ __forceinline__ ull pk2(float x, float y) {
    ull r; asm("mov.b64 %0, {%1, %2};" : "=l"(r) : "f"(x), "f"(y)); return r;
}
__device__ __forceinline__ ull dup2(float x) {
    ull r; asm("mov.b64 %0, {%1, %1};" : "=l"(r) : "f"(x)); return r;
}
__device__ __forceinline__ ull fma2(ull a, ull b, ull c) {
    ull d; asm("fma.rn.f32x2 %0, %1, %2, %3;" : "=l"(d) : "l"(a), "l"(b), "l"(c)); return d;
}
__device__ __forceinline__ void unpk2(ull v, float &x, float &y) {
    asm("mov.b64 {%0, %1}, %2;" : "=f"(x), "=f"(y) : "l"(v));
}

// Hs layout: column j (0..255) x 64 rows, as 16 float4 row-groups with an XOR
// swizzle so the transpose-write of the new h (indexed by output column) is
// only 4-way bank conflicted instead of 32-way. GEMM reads are warp-broadcast
// (all lanes same address) -> conflict-free.
__device__ __forceinline__ int hs_idx(int j, int g /*float4 group 0..15*/) {
    return j * 64 + ((g ^ ((j >> 2) & 15)) << 2);
}

// One reduction step k: rank-1 update of the 8x8 thread tile with packed FMAs.
__device__ __forceinline__ void mma_k(const float4 &h0, const float4 &h1,
                                      const float4 &ua, const float4 &ub,
                                      ull accA[8][2], ull accB[8][2]) {
    ull a01 = pk2(ua.x, ua.y), a23 = pk2(ua.z, ua.w);
    ull b01 = pk2(ub.x, ub.y), b23 = pk2(ub.z, ub.w);
    float hv[8] = {h0.x, h0.y, h0.z, h0.w, h1.x, h1.y, h1.z, h1.w};
#pragma unroll
    for (int r = 0; r < 8; ++r) {
        ull d = dup2(hv[r]);
        accA[r][0] = fma2(d, a01, accA[r][0]);
        accA[r][1] = fma2(d, a23, accA[r][1]);
        accB[r][0] = fma2(d, b01, accB[r][0]);
        accB[r][1] = fma2(d, b23, accB[r][1]);
    }
}

// acc(8x256 thread-tile slice) += h(64x256 slice in smem) @ M(256x256 row-major)
// Global M is prefetched distance-1 (L2 hit ~234-262 cyc ~= per-k wall time at
// 4 warps/SMSP). Smem h is NOT prefetched: LDS 29 cyc hides under the warp RR,
// and dropping it keeps us safely under the 128-reg cap of launch_bounds(256,2).
__device__ __forceinline__ void gemm256(const float* __restrict__ M,
                                        const float* __restrict__ Hs,
                                        int tx, int ty,
                                        ull accA[8][2], ull accB[8][2]) {
    const int ga = 2 * ty, gb = 2 * ty + 1;
    const float* Ma = M + 4 * tx;          // cols 4tx..4tx+3
    const float* Mb = M + 128 + 4 * tx;    // cols 128+4tx..+3
    float4 ua = *reinterpret_cast<const float4*>(Ma);
    float4 ub = *reinterpret_cast<const float4*>(Mb);
#pragma unroll 4
    for (int k = 0; k < H_SZ - 1; ++k) {
        float4 nua = *reinterpret_cast<const float4*>(Ma + (k + 1) * H_SZ);
        float4 nub = *reinterpret_cast<const float4*>(Mb + (k + 1) * H_SZ);
        float4 h0 = *reinterpret_cast<const float4*>(Hs + hs_idx(k, ga));
        float4 h1 = *reinterpret_cast<const float4*>(Hs + hs_idx(k, gb));
        mma_k(h0, h1, ua, ub, accA, accB);
        ua = nua; ub = nub;
    }
    {   // k = 255
        float4 h0 = *reinterpret_cast<const float4*>(Hs + hs_idx(H_SZ - 1, ga));
        float4 h1 = *reinterpret_cast<const float4*>(Hs + hs_idx(H_SZ - 1, gb));
        mma_k(h0, h1, ua, ub, accA, accB);
    }
}

__device__ __forceinline__ void init_acc(ull accA[8][2], ull accB[8][2],
                                         const float* __restrict__ bias,
                                         const float* __restrict__ W_in,
                                         const float* __restrict__ xs,
                                         int tx, int ty, bool withX) {
    float4 bA = *reinterpret_cast<const float4*>(bias + 4 * tx);
    float4 bB = *reinterpret_cast<const float4*>(bias + 128 + 4 * tx);
    ull bA01 = pk2(bA.x, bA.y), bA23 = pk2(bA.z, bA.w);
    ull bB01 = pk2(bB.x, bB.y), bB23 = pk2(bB.z, bB.w);
#pragma unroll
    for (int r = 0; r < 8; ++r) {
        accA[r][0] = bA01; accA[r][1] = bA23;
        accB[r][0] = bB01; accB[r][1] = bB23;
    }
    if (withX) {
#pragma unroll
        for (int f = 0; f < 3; ++f) {
            float4 wA = *reinterpret_cast<const float4*>(W_in + f * H_SZ + 4 * tx);
            float4 wB = *reinterpret_cast<const float4*>(W_in + f * H_SZ + 128 + 4 * tx);
            ull wA01 = pk2(wA.x, wA.y), wA23 = pk2(wA.z, wA.w);
            ull wB01 = pk2(wB.x, wB.y), wB23 = pk2(wB.z, wB.w);
#pragma unroll
            for (int r = 0; r < 8; ++r) {
                ull d = dup2(xs[f * CTA_ROWS + ty * 8 + r]);
                accA[r][0] = fma2(d, wA01, accA[r][0]);
                accA[r][1] = fma2(d, wA23, accA[r][1]);
                accB[r][0] = fma2(d, wB01, accB[r][0]);
                accB[r][1] = fma2(d, wB23, accB[r][1]);
            }
        }
    }
}

// relu + transpose-write new h into Hs (new h value for output column c).
__device__ __forceinline__ void store_h(float* __restrict__ Hs, int tx, int ty,
                                        ull accA[8][2], ull accB[8][2]) {
    const int g0 = 2 * ty, g1 = 2 * ty + 1;
#pragma unroll
    for (int half = 0; half < 2; ++half) {
        ull (*acc)[2] = half ? accB : accA;
        int c0 = half * 128 + 4 * tx;
#pragma unroll
        for (int cc = 0; cc < 4; ++cc) {
            int c = c0 + cc;
            float v[8];
#pragma unroll
            for (int r = 0; r < 8; ++r) {
                float lo, hi; unpk2(acc[r][cc >> 1], lo, hi);
                float x = (cc & 1) ? hi : lo;
                v[r] = fmaxf(x, 0.0f);
            }
            *reinterpret_cast<float4*>(Hs + hs_idx(c, g0)) = make_float4(v[0], v[1], v[2], v[3]);
            *reinterpret_cast<float4*>(Hs + hs_idx(c, g1)) = make_float4(v[4], v[5], v[6], v[7]);
        }
    }
}

__global__ void __launch_bounds__(NTHREADS, 2)
rnn_persistent_kernel(const float* __restrict__ x0, const float* __restrict__ x1,
                      const float* __restrict__ x2, const float* __restrict__ W_in,
                      const float* __restrict__ U,  const float* __restrict__ b_rnn,
                      const float* __restrict__ W_d, const float* __restrict__ b_d,
                      float* __restrict__ out) {
    extern __shared__ float sm[];
    float* Hs = sm;                       // 256 * 64 floats (swizzled h state)
    float* xs = sm + H_SZ * CTA_ROWS;     // 3 * 64 floats (this step's raw x)

    const int tid = threadIdx.x;
    const int tx = tid & 31;
    const int ty = tid >> 5;
    const int row_base = blockIdx.x * CTA_ROWS;

    // h0 = 0
    for (int i = tid; i < H_SZ * CTA_ROWS; i += NTHREADS) Hs[i] = 0.0f;

    ull accA[8][2], accB[8][2];

    for (int t = 0; t < T_SZ; ++t) {
        const int tt = T_SZ - 1 - t;  // time reversal x[:, ::-1, :]
        // stage this step's x values (3 features x 64 rows) into smem
        if (tid < 3 * CTA_ROWS) {
            int f = tid >> 6, r = tid & 63;
            const float* xp = (f == 0) ? x0 : (f == 1) ? x1 : x2;
            xs[tid] = xp[(size_t)(row_base + r) * T_SZ + tt];
        }
        __syncthreads();  // xs ready; also orders previous step's Hs writes

        init_acc(accA, accB, b_rnn, W_in, xs, tx, ty, true);  // xp_t + b_rnn
        gemm256(U, Hs, tx, ty, accA, accB);                   // + h @ U
        __syncthreads();                                      // all Hs reads done
        store_h(Hs, tx, ty, accA, accB);                      // h = relu(...)
    }
    __syncthreads();

    // out = hT @ W_d + b_d  (no relu)
    init_acc(accA, accB, b_d, W_in, xs, tx, ty, false);
    gemm256(W_d, Hs, tx, ty, accA, accB);
#pragma unroll
    for (int r = 0; r < 8; ++r) {
        float a0, a1, a2, a3, c0, c1, c2, c3;
        unpk2(accA[r][0], a0, a1); unpk2(accA[r][1], a2, a3);
        unpk2(accB[r][0], c0, c1); unpk2(accB[r][1], c2, c3);
        float* o = out + (size_t)(row_base + ty * 8 + r) * H_SZ;
        *reinterpret_cast<float4*>(o + 4 * tx)       = make_float4(a0, a1, a2, a3);
        *reinterpret_cast<float4*>(o + 128 + 4 * tx) = make_float4(c0, c1, c2, c3);
    }
}

extern "C" void kernel_launch(void* const* d_in, const int* in_sizes, int n_in,
                              void* d_out, int out_size) {
    (void)in_sizes; (void)n_in; (void)out_size;
    const float* x0    = (const float*)d_in[0];
    const float* x1    = (const float*)d_in[1];
    const float* x2    = (const float*)d_in[2];
    const float* W_in  = (const float*)d_in[3];
    const float* U     = (const float*)d_in[4];
    const float* b_rnn = (const float*)d_in[5];
    const float* W_d   = (const float*)d_in[6];
    const float* b_d   = (const float*)d_in[7];
    float* out = (float*)d_out;

    const int smem_bytes = (H_SZ * CTA_ROWS + 3 * CTA_ROWS) * (int)sizeof(float);  // 66304
    cudaFuncSetAttribute(rnn_persistent_kernel,
                         cudaFuncAttributeMaxDynamicSharedMemorySize, smem_bytes);

    rnn_persistent_kernel<<<NCTAS, NTHREADS, smem_bytes>>>(
        x0, x1, x2, W_in, U, b_rnn, W_d, b_d, out);
}

// round 6
// speedup vs baseline: 1.1225x; 1.1225x over previous
#include <cuda_runtime.h>

#define B_SZ   16384
#define T_SZ   79
#define H_SZ   256
#define CTA_ROWS 64
#define NTHREADS 256
#define NCTAS  (B_SZ / CTA_ROWS)   // 256

typedef unsigned long long ull;

// ---- packed f32x2 helpers (Blackwell FFMA2; only reachable via PTX f32x2) ----
__device__ __forceinline__ ull dup2(float x) {
    ull r; asm("mov.b64 %0, {%1, %1};" : "=l"(r) : "f"(x)); return r;
}
__device__ __forceinline__ ull fma2(ull a, ull b, ull c) {
    ull d; asm("fma.rn.f32x2 %0, %1, %2, %3;" : "=l"(d) : "l"(a), "l"(b), "l"(c)); return d;
}
__device__ __forceinline__ void unpk2(ull v, float &x, float &y) {
    asm("mov.b64 {%0, %1}, %2;" : "=f"(x), "=f"(y) : "l"(v));
}

// Hs layout: column j (0..255) x 64 rows as 16 float4 row-groups, XOR swizzle
// so the transposed store of new h is 4-way instead of 32-way conflicted.
// GEMM-side reads are warp-broadcast -> conflict-free.
__device__ __forceinline__ int hs_idx(int j, int g /*float4 group 0..15*/) {
    return j * 64 + ((g ^ ((j >> 2) & 15)) << 2);
}

// Rank-1 update of the 8x8 thread tile: U operands arrive pre-packed (no pk movs).
__device__ __forceinline__ void mma_k(const float4 &h0, const float4 &h1,
                                      const ulonglong2 &ua, const ulonglong2 &ub,
                                      ull accA[8][2], ull accB[8][2]) {
    float hv[8] = {h0.x, h0.y, h0.z, h0.w, h1.x, h1.y, h1.z, h1.w};
#pragma unroll
    for (int r = 0; r < 8; ++r) {
        ull d = dup2(hv[r]);
        accA[r][0] = fma2(d, ua.x, accA[r][0]);
        accA[r][1] = fma2(d, ua.y, accA[r][1]);
        accB[r][0] = fma2(d, ub.x, accB[r][0]);
        accB[r][1] = fma2(d, ub.y, accB[r][1]);
    }
}

// acc(8x256 thread tile) += h(64x256 in smem) @ M(256x256 row-major).
// Distance-1 prefetch on BOTH the global M stream (L2 ~234-262 cyc) and the
// smem h stream (LDS 29 cyc) so neither dependency is exposed at issue time.
// NOTE: row stride in ulonglong2 (16B) units is 256*4/16 = 64.  (R5 bug: used 32.)
#define M_ROW_U2 64
__device__ __forceinline__ void gemm256(const float* __restrict__ M,
                                        const float* __restrict__ Hs,
                                        int tx, int ty,
                                        ull accA[8][2], ull accB[8][2]) {
    const int ga = 2 * ty, gb = 2 * ty + 1;
    const ulonglong2* Ma = reinterpret_cast<const ulonglong2*>(M + 4 * tx);
    const ulonglong2* Mb = reinterpret_cast<const ulonglong2*>(M + 128 + 4 * tx);
    ulonglong2 ua = Ma[0];
    ulonglong2 ub = Mb[0];
    float4 h0 = *reinterpret_cast<const float4*>(Hs + hs_idx(0, ga));
    float4 h1 = *reinterpret_cast<const float4*>(Hs + hs_idx(0, gb));
#pragma unroll 8
    for (int k = 0; k < H_SZ - 1; ++k) {
        ulonglong2 nua = Ma[(k + 1) * M_ROW_U2];
        ulonglong2 nub = Mb[(k + 1) * M_ROW_U2];
        float4 nh0 = *reinterpret_cast<const float4*>(Hs + hs_idx(k + 1, ga));
        float4 nh1 = *reinterpret_cast<const float4*>(Hs + hs_idx(k + 1, gb));
        mma_k(h0, h1, ua, ub, accA, accB);
        ua = nua; ub = nub; h0 = nh0; h1 = nh1;
    }
    mma_k(h0, h1, ua, ub, accA, accB);  // k = 255
}

__device__ __forceinline__ void init_acc(ull accA[8][2], ull accB[8][2],
                                         const float* __restrict__ bias,
                                         const float* __restrict__ W_in,
                                         const float* __restrict__ xs,
                                         int tx, int ty, bool withX) {
    ulonglong2 bA = *reinterpret_cast<const ulonglong2*>(bias + 4 * tx);
    ulonglong2 bB = *reinterpret_cast<const ulonglong2*>(bias + 128 + 4 * tx);
#pragma unroll
    for (int r = 0; r < 8; ++r) {
        accA[r][0] = bA.x; accA[r][1] = bA.y;
        accB[r][0] = bB.x; accB[r][1] = bB.y;
    }
    if (withX) {
#pragma unroll
        for (int f = 0; f < 3; ++f) {
            ulonglong2 wA = *reinterpret_cast<const ulonglong2*>(W_in + f * H_SZ + 4 * tx);
            ulonglong2 wB = *reinterpret_cast<const ulonglong2*>(W_in + f * H_SZ + 128 + 4 * tx);
#pragma unroll
            for (int r = 0; r < 8; ++r) {
                ull d = dup2(xs[f * CTA_ROWS + ty * 8 + r]);
                accA[r][0] = fma2(d, wA.x, accA[r][0]);
                accA[r][1] = fma2(d, wA.y, accA[r][1]);
                accB[r][0] = fma2(d, wB.x, accB[r][0]);
                accB[r][1] = fma2(d, wB.y, accB[r][1]);
            }
        }
    }
}

// relu + transpose-write new h into Hs (new h value for output column c).
__device__ __forceinline__ void store_h(float* __restrict__ Hs, int tx, int ty,
                                        ull accA[8][2], ull accB[8][2]) {
    const int g0 = 2 * ty, g1 = 2 * ty + 1;
#pragma unroll
    for (int half = 0; half < 2; ++half) {
        ull (*acc)[2] = half ? accB : accA;
        int c0 = half * 128 + 4 * tx;
#pragma unroll
        for (int cp = 0; cp < 2; ++cp) {     // column pair within the 4
            float ve[8], vo[8];
#pragma unroll
            for (int r = 0; r < 8; ++r) {
                float lo, hi; unpk2(acc[r][cp], lo, hi);
                ve[r] = fmaxf(lo, 0.0f);
                vo[r] = fmaxf(hi, 0.0f);
            }
            int ce = c0 + 2 * cp, co = ce + 1;
            *reinterpret_cast<float4*>(Hs + hs_idx(ce, g0)) = make_float4(ve[0], ve[1], ve[2], ve[3]);
            *reinterpret_cast<float4*>(Hs + hs_idx(ce, g1)) = make_float4(ve[4], ve[5], ve[6], ve[7]);
            *reinterpret_cast<float4*>(Hs + hs_idx(co, g0)) = make_float4(vo[0], vo[1], vo[2], vo[3]);
            *reinterpret_cast<float4*>(Hs + hs_idx(co, g1)) = make_float4(vo[4], vo[5], vo[6], vo[7]);
        }
    }
}

__global__ void __launch_bounds__(NTHREADS, 2)
rnn_persistent_kernel(const float* __restrict__ x0, const float* __restrict__ x1,
                      const float* __restrict__ x2, const float* __restrict__ W_in,
                      const float* __restrict__ U,  const float* __restrict__ b_rnn,
                      const float* __restrict__ W_d, const float* __restrict__ b_d,
                      float* __restrict__ out) {
    extern __shared__ float sm[];
    float* Hs = sm;                       // 256 * 64 floats (swizzled h state)
    float* xs = sm + H_SZ * CTA_ROWS;     // 3 * 64 floats (this step's raw x)

    const int tid = threadIdx.x;
    const int tx = tid & 31;
    const int ty = tid >> 5;
    const int row_base = blockIdx.x * CTA_ROWS;

    // h0 = 0
    for (int i = tid; i < H_SZ * CTA_ROWS; i += NTHREADS) Hs[i] = 0.0f;

    // cross-step x prefetch: thread (f, r) owns one x value per step
    const bool xact = tid < 3 * CTA_ROWS;
    const float* xptr = nullptr;
    float xv = 0.0f;
    if (xact) {
        int f = tid >> 6, r = tid & 63;
        const float* xb = (f == 0) ? x0 : (f == 1) ? x1 : x2;
        xptr = xb + (size_t)(row_base + r) * T_SZ;
        xv = xptr[T_SZ - 1];  // step t=0 reads tt = T-1
    }

    ull accA[8][2], accB[8][2];

    for (int t = 0; t < T_SZ; ++t) {
        if (xact) xs[tid] = xv;   // publish this step's x
        __syncthreads();          // xs ready; also orders previous step's Hs writes
        if (xact && t + 1 < T_SZ) xv = xptr[T_SZ - 2 - t];  // prefetch next step (lands ~30K cyc later)

        init_acc(accA, accB, b_rnn, W_in, xs, tx, ty, true);  // xp_t + b_rnn
        gemm256(U, Hs, tx, ty, accA, accB);                   // + h @ U
        __syncthreads();                                      // all Hs reads done
        store_h(Hs, tx, ty, accA, accB);                      // h = relu(...)
    }
    __syncthreads();

    // out = hT @ W_d + b_d  (no relu)
    init_acc(accA, accB, b_d, W_in, xs, tx, ty, false);
    gemm256(W_d, Hs, tx, ty, accA, accB);
#pragma unroll
    for (int r = 0; r < 8; ++r) {
        float* o = out + (size_t)(row_base + ty * 8 + r) * H_SZ;
        // acc ulls are already {c, c+1} packed in column order -> store directly
        *reinterpret_cast<ulonglong2*>(o + 4 * tx)       = make_ulonglong2(accA[r][0], accA[r][1]);
        *reinterpret_cast<ulonglong2*>(o + 128 + 4 * tx) = make_ulonglong2(accB[r][0], accB[r][1]);
    }
}

extern "C" void kernel_launch(void* const* d_in, const int* in_sizes, int n_in,
                              void* d_out, int out_size) {
    (void)in_sizes; (void)n_in; (void)out_size;
    const float* x0    = (const float*)d_in[0];
    const float* x1    = (const float*)d_in[1];
    const float* x2    = (const float*)d_in[2];
    const float* W_in  = (const float*)d_in[3];
    const float* U     = (const float*)d_in[4];
    const float* b_rnn = (const float*)d_in[5];
    const float* W_d   = (const float*)d_in[6];
    const float* b_d   = (const float*)d_in[7];
    float* out = (float*)d_out;

    const int smem_bytes = (H_SZ * CTA_ROWS + 3 * CTA_ROWS) * (int)sizeof(float);  // 66304
    cudaFuncSetAttribute(rnn_persistent_kernel,
                         cudaFuncAttributeMaxDynamicSharedMemorySize, smem_bytes);

    rnn_persistent_kernel<<<NCTAS, NTHREADS, smem_bytes>>>(
        x0, x1, x2, W_in, U, b_rnn, W_d, b_d, out);
}